// round 3
// baseline (speedup 1.0000x reference)
#include <cuda_runtime.h>

// Problem constants
#define BB 4
#define SS 1024
#define DD 1024
#define HH 16
#define HD 64
#define N3D 3072          // 3*D
#define MM (BB*SS)        // 4096 rows of the GEMM

// Head-major scratch for Q/K/V: [B,H,S,HD]
__device__ float g_q[BB*HH*SS*HD];
__device__ float g_k[BB*HH*SS*HD];
__device__ float g_v[BB*HH*SS*HD];

// ---------------------------------------------------------------------------
// Kernel 1: qkv = x @ W + b, scattered into head-major q/k/v.
// Tile: 64(M) x 64(N), K-chunk 16. Block 16x16 threads, 4x4 per thread.
// Q is pre-scaled by 1/sqrt(HD) = 0.125 so attention does a plain dot product.
// ---------------------------------------------------------------------------
__global__ void qkv_gemm_kernel(const float* __restrict__ x,
                                const float* __restrict__ W,
                                const float* __restrict__ bias) {
    __shared__ float As[16][68];   // [k][m], padded against write conflicts
    __shared__ float Bs[16][64];   // [k][n]

    const int tx = threadIdx.x;    // 0..15 -> N
    const int ty = threadIdx.y;    // 0..15 -> M
    const int tid = ty * 16 + tx;  // 0..255
    const int tileN = blockIdx.x * 64;
    const int tileM = blockIdx.y * 64;

    float acc[4][4];
#pragma unroll
    for (int i = 0; i < 4; i++)
#pragma unroll
        for (int j = 0; j < 4; j++) acc[i][j] = 0.0f;

    for (int k0 = 0; k0 < DD; k0 += 16) {
        // Load A tile (64 rows x 16 k) transposed into As[k][m]
#pragma unroll
        for (int e = tid; e < 1024; e += 256) {
            int m = e >> 4;           // 0..63
            int kk = e & 15;          // 0..15
            As[kk][m] = x[(size_t)(tileM + m) * DD + k0 + kk];
        }
        // Load B tile (16 k x 64 n)
#pragma unroll
        for (int e = tid; e < 1024; e += 256) {
            int kk = e >> 6;          // 0..15
            int nn = e & 63;          // 0..63
            Bs[kk][nn] = W[(size_t)(k0 + kk) * N3D + tileN + nn];
        }
        __syncthreads();

#pragma unroll
        for (int kk = 0; kk < 16; kk++) {
            float4 a4 = *reinterpret_cast<const float4*>(&As[kk][ty * 4]);
            float4 b4 = *reinterpret_cast<const float4*>(&Bs[kk][tx * 4]);
            float av[4] = {a4.x, a4.y, a4.z, a4.w};
            float bv[4] = {b4.x, b4.y, b4.z, b4.w};
#pragma unroll
            for (int i = 0; i < 4; i++)
#pragma unroll
                for (int j = 0; j < 4; j++)
                    acc[i][j] += av[i] * bv[j];
        }
        __syncthreads();
    }

    // Epilogue: add bias, scatter to head-major q (scaled), k, v.
#pragma unroll
    for (int i = 0; i < 4; i++) {
        int m = tileM + ty * 4 + i;
        int b = m >> 10;          // m / S
        int s = m & 1023;         // m % S
#pragma unroll
        for (int j = 0; j < 4; j++) {
            int col = tileN + tx * 4 + j;
            float val = acc[i][j] + bias[col];
            int h = col / 192;          // 3*HD = 192 per head
            int c = col - h * 192;
            size_t base = ((size_t)(b * HH + h) * SS + s) * HD;
            if (c < 64)       g_q[base + c]        = val * 0.125f;  // fold 1/sqrt(64)
            else if (c < 128) g_k[base + c - 64]   = val;
            else              g_v[base + c - 128]  = val;
        }
    }
}

// ---------------------------------------------------------------------------
// Kernel 2: flash-attention per (b,h). Block = 128 query rows, 1 row/thread.
// K/V tiles of 64 keys staged in smem; online softmax per row.
// blockIdx.x = b*H+h (64), blockIdx.y = q-tile (8). blockDim = 128.
// ---------------------------------------------------------------------------
__global__ void attn_kernel(float* __restrict__ out) {
    __shared__ float Ks[64][64];
    __shared__ float Vs[64][64];

    const int bh = blockIdx.x;                 // 0..63
    const int r  = blockIdx.y * 128 + threadIdx.x;  // query row 0..1023

    // Load this row's (pre-scaled) query into registers
    float q[HD];
    {
        const float4* qp = reinterpret_cast<const float4*>(&g_q[((size_t)bh * SS + r) * HD]);
#pragma unroll
        for (int i = 0; i < 16; i++) {
            float4 v = qp[i];
            q[4*i+0] = v.x; q[4*i+1] = v.y; q[4*i+2] = v.z; q[4*i+3] = v.w;
        }
    }

    float o[HD];
#pragma unroll
    for (int d = 0; d < HD; d++) o[d] = 0.0f;
    float mmax = -1e30f;
    float lsum = 0.0f;

    for (int kt = 0; kt < SS / 64; kt++) {
        __syncthreads();
        // Stage K and V tiles (64 x 64 each, contiguous in head-major layout)
        {
            const float4* kp = reinterpret_cast<const float4*>(&g_k[((size_t)bh * SS + kt * 64) * HD]);
            const float4* vp = reinterpret_cast<const float4*>(&g_v[((size_t)bh * SS + kt * 64) * HD]);
            float4* ks = reinterpret_cast<float4*>(&Ks[0][0]);
            float4* vs = reinterpret_cast<float4*>(&Vs[0][0]);
#pragma unroll
            for (int e = threadIdx.x; e < 1024; e += 128) {
                ks[e] = kp[e];
                vs[e] = vp[e];
            }
        }
        __syncthreads();

        for (int j = 0; j < 64; j++) {
            // s = q . K_j  (Ks row is a broadcast across the warp -> conflict-free)
            float s = 0.0f;
#pragma unroll
            for (int d4 = 0; d4 < 16; d4++) {
                float4 kv = *reinterpret_cast<const float4*>(&Ks[j][d4 * 4]);
                s += q[4*d4+0] * kv.x + q[4*d4+1] * kv.y
                   + q[4*d4+2] * kv.z + q[4*d4+3] * kv.w;
            }

            if (s > mmax) {
                // rare path: new running max -> rescale accumulator
                float corr = __expf(mmax - s);
                lsum = lsum * corr + 1.0f;
#pragma unroll
                for (int d4 = 0; d4 < 16; d4++) {
                    float4 vv = *reinterpret_cast<const float4*>(&Vs[j][d4 * 4]);
                    o[4*d4+0] = o[4*d4+0] * corr + vv.x;
                    o[4*d4+1] = o[4*d4+1] * corr + vv.y;
                    o[4*d4+2] = o[4*d4+2] * corr + vv.z;
                    o[4*d4+3] = o[4*d4+3] * corr + vv.w;
                }
                mmax = s;
            } else {
                float p = __expf(s - mmax);
                lsum += p;
#pragma unroll
                for (int d4 = 0; d4 < 16; d4++) {
                    float4 vv = *reinterpret_cast<const float4*>(&Vs[j][d4 * 4]);
                    o[4*d4+0] += p * vv.x;
                    o[4*d4+1] += p * vv.y;
                    o[4*d4+2] += p * vv.z;
                    o[4*d4+3] += p * vv.w;
                }
            }
        }
    }

    // Write output: out[b, r, h*64 + d]
    const int b = bh / HH;
    const int h = bh % HH;
    float inv_l = 1.0f / lsum;
    float4* op = reinterpret_cast<float4*>(&out[((size_t)b * SS + r) * DD + h * HD]);
#pragma unroll
    for (int d4 = 0; d4 < 16; d4++) {
        float4 v;
        v.x = o[4*d4+0] * inv_l;
        v.y = o[4*d4+1] * inv_l;
        v.z = o[4*d4+2] * inv_l;
        v.w = o[4*d4+3] * inv_l;
        op[d4] = v;
    }
}

extern "C" void kernel_launch(void* const* d_in, const int* in_sizes, int n_in,
                              void* d_out, int out_size) {
    const float* x    = (const float*)d_in[0];   // [B,S,D]
    const float* Wq   = (const float*)d_in[1];   // [D,3D]
    const float* bq   = (const float*)d_in[2];   // [3D]
    float* out        = (float*)d_out;           // [B,S,D]

    dim3 gridG(N3D / 64, MM / 64);   // (48, 64)
    dim3 blockG(16, 16);
    qkv_gemm_kernel<<<gridG, blockG>>>(x, Wq, bq);

    dim3 gridA(BB * HH, SS / 128);   // (64, 8)
    attn_kernel<<<gridA, 128>>>(out);
}